// round 7
// baseline (speedup 1.0000x reference)
#include <cuda_runtime.h>
#include <cuda_bf16.h>
#include <cuda_fp16.h>
#include <cstdint>

// Sliding-window attention via mma.sync. S: bf16 3-term split (~fp32 exact).
// PV: fp16, P split hi/lo (2 terms), V single fp16 array -> O rel err ~1.4e-4.
// B=1, H=16, S=8192, D=64, window read on device.

static constexpr int HH  = 16;
static constexpr int SEQ = 8192;
static constexpr int DD  = 64;
static constexpr int BQ  = 64;
static constexpr int BK  = 64;
static constexpr size_t KVN = (size_t)HH * SEQ * DD;   // 8388608

__device__ __nv_bfloat16 g_kh[KVN];
__device__ __nv_bfloat16 g_kl[KVN];
__device__ __half        g_vh[KVN];

// ---------------- helpers ----------------
__device__ __forceinline__ uint32_t f2bf(float x) {
    uint32_t u = __float_as_uint(x);
    return (u + 0x7fffu + ((u >> 16) & 1u)) >> 16;
}
__device__ __forceinline__ float bf2f(uint32_t b) { return __uint_as_float(b << 16); }

// bf16x2 pack: upper = a, lower = b
__device__ __forceinline__ uint32_t cvt2(float a, float b) {
    uint32_t d;
    asm("cvt.rn.bf16x2.f32 %0, %1, %2;" : "=r"(d) : "f"(a), "f"(b));
    return d;
}
// fp16x2 pack: lower = a, upper = b
__device__ __forceinline__ uint32_t h2pack(float a, float b) {
    __half2 h = __floats2half2_rn(a, b);
    return *(uint32_t*)&h;
}
__device__ __forceinline__ float2 h2unpack(uint32_t u) {
    __half2 h = *(__half2*)&u;
    return __half22float2(h);
}
__device__ __forceinline__ float ex2f(float x) {
    float r;
    asm("ex2.approx.f32 %0, %1;" : "=f"(r) : "f"(x));
    return r;
}

__device__ __forceinline__ uint32_t smem_u32(const void* p) {
    uint32_t a;
    asm("{ .reg .u64 t; cvta.to.shared.u64 t, %1; cvt.u32.u64 %0, t; }" : "=r"(a) : "l"(p));
    return a;
}
#define SWZ(x) ((x) ^ (((x) >> 3) & 0x70))

__device__ __forceinline__ void cpasync16(uint32_t dst, const void* src, int sz) {
    asm volatile("cp.async.cg.shared.global [%0], [%1], 16, %2;"
                 :: "r"(dst), "l"(src), "r"(sz) : "memory");
}
#define CP_COMMIT() asm volatile("cp.async.commit_group;" ::: "memory")
#define CP_WAIT0()  asm volatile("cp.async.wait_group 0;" ::: "memory")

__device__ __forceinline__ void ldsm4(uint32_t& r0, uint32_t& r1, uint32_t& r2, uint32_t& r3,
                                      uint32_t addr) {
    asm volatile("ldmatrix.sync.aligned.m8n8.x4.shared.b16 {%0,%1,%2,%3}, [%4];"
                 : "=r"(r0), "=r"(r1), "=r"(r2), "=r"(r3) : "r"(addr));
}
__device__ __forceinline__ void ldsm4t(uint32_t& r0, uint32_t& r1, uint32_t& r2, uint32_t& r3,
                                       uint32_t addr) {
    asm volatile("ldmatrix.sync.aligned.m8n8.x4.trans.shared.b16 {%0,%1,%2,%3}, [%4];"
                 : "=r"(r0), "=r"(r1), "=r"(r2), "=r"(r3) : "r"(addr));
}
__device__ __forceinline__ void mma_bf(float* c, const uint32_t* a, const uint32_t* b) {
    asm volatile("mma.sync.aligned.m16n8k16.row.col.f32.bf16.bf16.f32 "
                 "{%0,%1,%2,%3}, {%4,%5,%6,%7}, {%8,%9}, {%0,%1,%2,%3};"
                 : "+f"(c[0]), "+f"(c[1]), "+f"(c[2]), "+f"(c[3])
                 : "r"(a[0]), "r"(a[1]), "r"(a[2]), "r"(a[3]), "r"(b[0]), "r"(b[1]));
}
__device__ __forceinline__ void mma_fp(float* c, const uint32_t* a, const uint32_t* b) {
    asm volatile("mma.sync.aligned.m16n8k16.row.col.f32.f16.f16.f32 "
                 "{%0,%1,%2,%3}, {%4,%5,%6,%7}, {%8,%9}, {%0,%1,%2,%3};"
                 : "+f"(c[0]), "+f"(c[1]), "+f"(c[2]), "+f"(c[3])
                 : "r"(a[0]), "r"(a[1]), "r"(a[2]), "r"(a[3]), "r"(b[0]), "r"(b[1]));
}

// ---------------- prepass: K fp32 -> bf16 hi/lo, V fp32 -> fp16 ----------------
__global__ void prepass_kernel(const float* __restrict__ K, const float* __restrict__ V) {
    size_t i = ((size_t)blockIdx.x * 256 + threadIdx.x) * 4;
    float4 k4 = *(const float4*)(K + i);
    float4 v4 = *(const float4*)(V + i);

    uint32_t kh0 = f2bf(k4.x), kh1 = f2bf(k4.y), kh2 = f2bf(k4.z), kh3 = f2bf(k4.w);
    uint2 khp = make_uint2(kh0 | (kh1 << 16), kh2 | (kh3 << 16));
    uint2 klp = make_uint2(f2bf(k4.x - bf2f(kh0)) | (f2bf(k4.y - bf2f(kh1)) << 16),
                           f2bf(k4.z - bf2f(kh2)) | (f2bf(k4.w - bf2f(kh3)) << 16));
    uint2 vhp = make_uint2(h2pack(v4.x, v4.y), h2pack(v4.z, v4.w));

    ((uint2*)g_kh)[i >> 2] = khp;
    ((uint2*)g_kl)[i >> 2] = klp;
    ((uint2*)g_vh)[i >> 2] = vhp;
}

// ---------------- main kernel ----------------
static constexpr int STG = 24576;
static constexpr int OKH = 0, OKL = 8192, OVH = 16384;
static constexpr int SMEM_BYTES = 2 * STG;   // 49152
// D^-1/2 * log2(e)
#define QSCALE 0.1803368801111204f

__device__ __forceinline__ void load_tile(uint32_t st, int h, int ts, int tid) {
#pragma unroll
    for (int c = 0; c < 4; c++) {
        int chunk = tid + 128 * c;
        int row = chunk >> 3;
        int col = (chunk & 7) * 16;
        int g = ts + row;
        bool ok = (unsigned)g < (unsigned)SEQ;
        int sz = ok ? 16 : 0;
        int gc = ok ? g : 0;
        size_t off = (((size_t)h * SEQ + gc) * DD) * 2 + col;
        uint32_t d = st + SWZ(row * 128 + col);
        cpasync16(d + OKH, (const char*)g_kh + off, sz);
        cpasync16(d + OKL, (const char*)g_kl + off, sz);
        cpasync16(d + OVH, (const char*)g_vh + off, sz);
    }
}

__global__ __launch_bounds__(128)
void swa_mma_kernel(const float* __restrict__ Q,
                    const int*   __restrict__ wptr,
                    float*       __restrict__ O)
{
    extern __shared__ char smem[];
    const uint32_t sb = smem_u32(smem);
    const int tid = threadIdx.x;
    const int wid = tid >> 5, lane = tid & 31;
    const int gid = lane >> 2, tig = lane & 3;
    const int h  = blockIdx.y;
    const int qs = blockIdx.x * BQ;
    const int w  = *wptr;

    // ---- Q fragments (scaled, split bf16 hi/lo) ----
    uint32_t qh[4][4], ql[4][4];
    {
        const float* qb = Q + ((size_t)h * SEQ + qs) * DD;
        int m0 = wid * 16 + gid;
#pragma unroll
        for (int ks = 0; ks < 4; ks++) {
            int c = ks * 16 + 2 * tig;
#pragma unroll
            for (int half = 0; half < 2; half++)
#pragma unroll
                for (int rh = 0; rh < 2; rh++) {
                    const float* p = qb + (m0 + rh * 8) * DD + c + half * 8;
                    float x0 = p[0] * QSCALE, x1 = p[1] * QSCALE;
                    uint32_t H = cvt2(x1, x0);
                    float e0 = x0 - __uint_as_float(H << 16);
                    float e1 = x1 - __uint_as_float(H & 0xffff0000u);
                    int idx = half * 2 + rh;
                    qh[ks][idx] = H;
                    ql[ks][idx] = cvt2(e1, e0);
                }
        }
    }

    float o[8][4];
#pragma unroll
    for (int j = 0; j < 8; j++)
#pragma unroll
        for (int k = 0; k < 4; k++) o[j][k] = 0.f;
    float l0 = 0.f, l1 = 0.f;

    const int r0 = qs + wid * 16 + gid, r1 = r0 + 8;
    int lo0 = r0 - w; if (lo0 < 0) lo0 = 0;
    int hi0 = r0 + w; if (hi0 > SEQ - 1) hi0 = SEQ - 1;
    int lo1 = r1 - w; if (lo1 < 0) lo1 = 0;
    int hi1 = r1 + w; if (hi1 > SEQ - 1) hi1 = SEQ - 1;

    const int Rw = qs + wid * 16;
    int Rlo = Rw - w;      if (Rlo < 0) Rlo = 0;
    int Rhi = Rw + 15 + w; if (Rhi > SEQ - 1) Rhi = SEQ - 1;

    const int T = (BQ + 2 * w + BK - 1) / BK;
    int i0 = 0; while (qs - w + i0 * BK + BK <= 0) i0++;
    int i1 = T - 1; while (qs - w + i1 * BK >= SEQ) i1--;

    load_tile(sb, h, qs - w + i0 * BK, tid);
    CP_COMMIT();

    const int mi = lane >> 3, rr = lane & 7;
    const int keyo = ((mi >> 1) & 1) * 8 + rr;
    const int dbq  = (mi & 1) * 16;
    const int keyq = (mi & 1) * 8 + rr;
    const int db2  = ((mi >> 1) & 1) * 16;

    for (int i = i0; i <= i1; i++) {
        int ts = qs - w + i * BK;
        uint32_t st = sb + ((i - i0) & 1) * STG;
        CP_WAIT0();
        __syncthreads();
        if (i < i1) { load_tile(sb + ((i - i0 + 1) & 1) * STG, h, ts + BK, tid); CP_COMMIT(); }

        int jjlo = (Rlo - ts) >> 4; if (jjlo < 0) jjlo = 0;
        int jjhi = (Rhi - ts) >> 4; if (jjhi > 3) jjhi = 3;

        // ---- S = Qh*Kh + Ql*Kh + Qh*Kl  (bf16) ----
        float s[8][4];
#pragma unroll
        for (int j = 0; j < 8; j++)
#pragma unroll
            for (int k = 0; k < 4; k++) s[j][k] = 0.f;

#pragma unroll
        for (int ks = 0; ks < 4; ks++) {
            int db = 32 * ks + dbq;
#pragma unroll
            for (int jj = 0; jj < 4; jj++) {
                if (jj < jjlo || jj > jjhi) continue;
                uint32_t a = st + OKH + SWZ((16 * jj + keyo) * 128 + db);
                uint32_t kh0[2], kh1[2], kl0[2], kl1[2];
                ldsm4(kh0[0], kh0[1], kh1[0], kh1[1], a);
                ldsm4(kl0[0], kl0[1], kl1[0], kl1[1], a + OKL);
                mma_bf(s[2*jj],   qh[ks], kh0);
                mma_bf(s[2*jj+1], qh[ks], kh1);
                mma_bf(s[2*jj],   ql[ks], kh0);
                mma_bf(s[2*jj+1], ql[ks], kh1);
                mma_bf(s[2*jj],   qh[ks], kl0);
                mma_bf(s[2*jj+1], qh[ks], kl1);
            }
        }

        // ---- mask + exp2 + split P into fp16 hi/lo ----
        uint32_t pah[8][2], pal[8][2];
#pragma unroll
        for (int j = 0; j < 8; j++) {
            int c0 = ts + 8 * j + 2 * tig, c1 = c0 + 1;
            float p00 = (c0 >= lo0 && c0 <= hi0) ? ex2f(s[j][0]) : 0.f;
            float p01 = (c1 >= lo0 && c1 <= hi0) ? ex2f(s[j][1]) : 0.f;
            float p10 = (c0 >= lo1 && c0 <= hi1) ? ex2f(s[j][2]) : 0.f;
            float p11 = (c1 >= lo1 && c1 <= hi1) ? ex2f(s[j][3]) : 0.f;
            l0 += p00 + p01; l1 += p10 + p11;
            uint32_t H0 = h2pack(p00, p01);
            uint32_t H1 = h2pack(p10, p11);
            float2 f0 = h2unpack(H0), f1 = h2unpack(H1);
            pah[j][0] = H0; pah[j][1] = H1;
            pal[j][0] = h2pack(p00 - f0.x, p01 - f0.y);
            pal[j][1] = h2pack(p10 - f1.x, p11 - f1.y);
        }

        // ---- O += (Ph + Pl) * Vh  (fp16) ----
#pragma unroll
        for (int ks = 0; ks < 4; ks++) {
            if (ks < jjlo || ks > jjhi) continue;
            int keyr = 16 * ks + keyq;
            uint32_t Ah[4] = {pah[2*ks][0], pah[2*ks][1], pah[2*ks+1][0], pah[2*ks+1][1]};
            uint32_t Al[4] = {pal[2*ks][0], pal[2*ks][1], pal[2*ks+1][0], pal[2*ks+1][1]};
#pragma unroll
            for (int jj = 0; jj < 4; jj++) {
                uint32_t a = st + OVH + SWZ(keyr * 128 + 32 * jj + db2);
                uint32_t vh0[2], vh1[2];
                ldsm4t(vh0[0], vh0[1], vh1[0], vh1[1], a);
                mma_fp(o[2*jj],   Ah, vh0);
                mma_fp(o[2*jj+1], Ah, vh1);
                mma_fp(o[2*jj],   Al, vh0);
                mma_fp(o[2*jj+1], Al, vh1);
            }
        }
    }

    // ---- epilogue ----
    l0 += __shfl_xor_sync(0xffffffffu, l0, 1);
    l0 += __shfl_xor_sync(0xffffffffu, l0, 2);
    l1 += __shfl_xor_sync(0xffffffffu, l1, 1);
    l1 += __shfl_xor_sync(0xffffffffu, l1, 2);
    float inv0 = 1.0f / l0, inv1 = 1.0f / l1;

    float* ob0 = O + ((size_t)h * SEQ + r0) * DD;
    float* ob1 = O + ((size_t)h * SEQ + r1) * DD;
#pragma unroll
    for (int j = 0; j < 8; j++) {
        *(float2*)(ob0 + 8 * j + 2 * tig) = make_float2(o[j][0] * inv0, o[j][1] * inv0);
        *(float2*)(ob1 + 8 * j + 2 * tig) = make_float2(o[j][2] * inv1, o[j][3] * inv1);
    }
}

extern "C" void kernel_launch(void* const* d_in, const int* in_sizes, int n_in,
                              void* d_out, int out_size)
{
    const float* q = (const float*)d_in[0];
    const float* k = (const float*)d_in[1];
    const float* v = (const float*)d_in[2];
    const int* wsz = (const int*)d_in[4];
    float* out = (float*)d_out;

    prepass_kernel<<<(int)(KVN / 1024), 256>>>(k, v);

    cudaFuncSetAttribute(swa_mma_kernel,
                         cudaFuncAttributeMaxDynamicSharedMemorySize, SMEM_BYTES);
    dim3 grid(SEQ / BQ, HH);   // (128, 16)
    swa_mma_kernel<<<grid, 128, SMEM_BYTES>>>(q, wsz, out);
}

// round 8
// speedup vs baseline: 1.2694x; 1.2694x over previous
#include <cuda_runtime.h>
#include <cuda_bf16.h>
#include <cuda_fp16.h>
#include <cstdint>

// Sliding-window attention via mma.sync. S: bf16 3-term split (~fp32 exact).
// PV: fp16 (P hi/lo 2-term, V fp16). R8: per-16-key-group pipeline to cut
// register pressure + __launch_bounds__(128,4) for 4 CTAs/SM.
// B=1, H=16, S=8192, D=64, window read on device.

static constexpr int HH  = 16;
static constexpr int SEQ = 8192;
static constexpr int DD  = 64;
static constexpr int BQ  = 64;
static constexpr int BK  = 64;
static constexpr size_t KVN = (size_t)HH * SEQ * DD;   // 8388608

__device__ __nv_bfloat16 g_kh[KVN];
__device__ __nv_bfloat16 g_kl[KVN];
__device__ __half        g_vh[KVN];

// ---------------- helpers ----------------
__device__ __forceinline__ uint32_t f2bf(float x) {
    uint32_t u = __float_as_uint(x);
    return (u + 0x7fffu + ((u >> 16) & 1u)) >> 16;
}
__device__ __forceinline__ float bf2f(uint32_t b) { return __uint_as_float(b << 16); }

// bf16x2 pack: upper = a, lower = b
__device__ __forceinline__ uint32_t cvt2(float a, float b) {
    uint32_t d;
    asm("cvt.rn.bf16x2.f32 %0, %1, %2;" : "=r"(d) : "f"(a), "f"(b));
    return d;
}
// fp16x2 pack: lower = a, upper = b
__device__ __forceinline__ uint32_t h2pack(float a, float b) {
    __half2 h = __floats2half2_rn(a, b);
    return *(uint32_t*)&h;
}
__device__ __forceinline__ float2 h2unpack(uint32_t u) {
    __half2 h = *(__half2*)&u;
    return __half22float2(h);
}
__device__ __forceinline__ float ex2f(float x) {
    float r;
    asm("ex2.approx.f32 %0, %1;" : "=f"(r) : "f"(x));
    return r;
}

__device__ __forceinline__ uint32_t smem_u32(const void* p) {
    uint32_t a;
    asm("{ .reg .u64 t; cvta.to.shared.u64 t, %1; cvt.u32.u64 %0, t; }" : "=r"(a) : "l"(p));
    return a;
}
#define SWZ(x) ((x) ^ (((x) >> 3) & 0x70))

__device__ __forceinline__ void cpasync16(uint32_t dst, const void* src, int sz) {
    asm volatile("cp.async.cg.shared.global [%0], [%1], 16, %2;"
                 :: "r"(dst), "l"(src), "r"(sz) : "memory");
}
#define CP_COMMIT() asm volatile("cp.async.commit_group;" ::: "memory")
#define CP_WAIT0()  asm volatile("cp.async.wait_group 0;" ::: "memory")

__device__ __forceinline__ void ldsm4(uint32_t& r0, uint32_t& r1, uint32_t& r2, uint32_t& r3,
                                      uint32_t addr) {
    asm volatile("ldmatrix.sync.aligned.m8n8.x4.shared.b16 {%0,%1,%2,%3}, [%4];"
                 : "=r"(r0), "=r"(r1), "=r"(r2), "=r"(r3) : "r"(addr));
}
__device__ __forceinline__ void ldsm4t(uint32_t& r0, uint32_t& r1, uint32_t& r2, uint32_t& r3,
                                       uint32_t addr) {
    asm volatile("ldmatrix.sync.aligned.m8n8.x4.trans.shared.b16 {%0,%1,%2,%3}, [%4];"
                 : "=r"(r0), "=r"(r1), "=r"(r2), "=r"(r3) : "r"(addr));
}
__device__ __forceinline__ void mma_bf(float* c, const uint32_t* a, const uint32_t* b) {
    asm volatile("mma.sync.aligned.m16n8k16.row.col.f32.bf16.bf16.f32 "
                 "{%0,%1,%2,%3}, {%4,%5,%6,%7}, {%8,%9}, {%0,%1,%2,%3};"
                 : "+f"(c[0]), "+f"(c[1]), "+f"(c[2]), "+f"(c[3])
                 : "r"(a[0]), "r"(a[1]), "r"(a[2]), "r"(a[3]), "r"(b[0]), "r"(b[1]));
}
__device__ __forceinline__ void mma_fp(float* c, const uint32_t* a, const uint32_t* b) {
    asm volatile("mma.sync.aligned.m16n8k16.row.col.f32.f16.f16.f32 "
                 "{%0,%1,%2,%3}, {%4,%5,%6,%7}, {%8,%9}, {%0,%1,%2,%3};"
                 : "+f"(c[0]), "+f"(c[1]), "+f"(c[2]), "+f"(c[3])
                 : "r"(a[0]), "r"(a[1]), "r"(a[2]), "r"(a[3]), "r"(b[0]), "r"(b[1]));
}

// ---------------- prepass: K fp32 -> bf16 hi/lo, V fp32 -> fp16 ----------------
__global__ void prepass_kernel(const float* __restrict__ K, const float* __restrict__ V) {
    size_t i = ((size_t)blockIdx.x * 256 + threadIdx.x) * 4;
    float4 k4 = *(const float4*)(K + i);
    float4 v4 = *(const float4*)(V + i);

    uint32_t kh0 = f2bf(k4.x), kh1 = f2bf(k4.y), kh2 = f2bf(k4.z), kh3 = f2bf(k4.w);
    uint2 khp = make_uint2(kh0 | (kh1 << 16), kh2 | (kh3 << 16));
    uint2 klp = make_uint2(f2bf(k4.x - bf2f(kh0)) | (f2bf(k4.y - bf2f(kh1)) << 16),
                           f2bf(k4.z - bf2f(kh2)) | (f2bf(k4.w - bf2f(kh3)) << 16));
    uint2 vhp = make_uint2(h2pack(v4.x, v4.y), h2pack(v4.z, v4.w));

    ((uint2*)g_kh)[i >> 2] = khp;
    ((uint2*)g_kl)[i >> 2] = klp;
    ((uint2*)g_vh)[i >> 2] = vhp;
}

// ---------------- main kernel ----------------
static constexpr int STG = 24576;
static constexpr int OKH = 0, OKL = 8192, OVH = 16384;
static constexpr int SMEM_BYTES = 2 * STG;   // 49152
// D^-1/2 * log2(e)
#define QSCALE 0.1803368801111204f

__device__ __forceinline__ void load_tile(uint32_t st, int h, int ts, int tid) {
#pragma unroll
    for (int c = 0; c < 4; c++) {
        int chunk = tid + 128 * c;
        int row = chunk >> 3;
        int col = (chunk & 7) * 16;
        int g = ts + row;
        bool ok = (unsigned)g < (unsigned)SEQ;
        int sz = ok ? 16 : 0;
        int gc = ok ? g : 0;
        size_t off = (((size_t)h * SEQ + gc) * DD) * 2 + col;
        uint32_t d = st + SWZ(row * 128 + col);
        cpasync16(d + OKH, (const char*)g_kh + off, sz);
        cpasync16(d + OKL, (const char*)g_kl + off, sz);
        cpasync16(d + OVH, (const char*)g_vh + off, sz);
    }
}

__global__ __launch_bounds__(128, 4)
void swa_mma_kernel(const float* __restrict__ Q,
                    const int*   __restrict__ wptr,
                    float*       __restrict__ O)
{
    extern __shared__ char smem[];
    const uint32_t sb = smem_u32(smem);
    const int tid = threadIdx.x;
    const int wid = tid >> 5, lane = tid & 31;
    const int gid = lane >> 2, tig = lane & 3;
    const int h  = blockIdx.y;
    const int qs = blockIdx.x * BQ;
    const int w  = *wptr;

    // ---- Q fragments (scaled, split bf16 hi/lo) ----
    uint32_t qh[4][4], ql[4][4];
    {
        const float* qb = Q + ((size_t)h * SEQ + qs) * DD;
        int m0 = wid * 16 + gid;
#pragma unroll
        for (int ks = 0; ks < 4; ks++) {
            int c = ks * 16 + 2 * tig;
#pragma unroll
            for (int half = 0; half < 2; half++)
#pragma unroll
                for (int rh = 0; rh < 2; rh++) {
                    const float* p = qb + (m0 + rh * 8) * DD + c + half * 8;
                    float x0 = p[0] * QSCALE, x1 = p[1] * QSCALE;
                    uint32_t H = cvt2(x1, x0);
                    float e0 = x0 - __uint_as_float(H << 16);
                    float e1 = x1 - __uint_as_float(H & 0xffff0000u);
                    int idx = half * 2 + rh;
                    qh[ks][idx] = H;
                    ql[ks][idx] = cvt2(e1, e0);
                }
        }
    }

    float o[8][4];
#pragma unroll
    for (int j = 0; j < 8; j++)
#pragma unroll
        for (int k = 0; k < 4; k++) o[j][k] = 0.f;
    float l0 = 0.f, l1 = 0.f;

    const int r0 = qs + wid * 16 + gid, r1 = r0 + 8;
    int lo0 = r0 - w; if (lo0 < 0) lo0 = 0;
    int hi0 = r0 + w; if (hi0 > SEQ - 1) hi0 = SEQ - 1;
    int lo1 = r1 - w; if (lo1 < 0) lo1 = 0;
    int hi1 = r1 + w; if (hi1 > SEQ - 1) hi1 = SEQ - 1;

    const int Rw = qs + wid * 16;
    int Rlo = Rw - w;      if (Rlo < 0) Rlo = 0;
    int Rhi = Rw + 15 + w; if (Rhi > SEQ - 1) Rhi = SEQ - 1;

    const int T = (BQ + 2 * w + BK - 1) / BK;
    int i0 = 0; while (qs - w + i0 * BK + BK <= 0) i0++;
    int i1 = T - 1; while (qs - w + i1 * BK >= SEQ) i1--;

    load_tile(sb, h, qs - w + i0 * BK, tid);
    CP_COMMIT();

    const int mi = lane >> 3, rr = lane & 7;
    const int keyo = ((mi >> 1) & 1) * 8 + rr;
    const int dbq  = (mi & 1) * 16;
    const int keyq = (mi & 1) * 8 + rr;
    const int db2  = ((mi >> 1) & 1) * 16;

    for (int i = i0; i <= i1; i++) {
        int ts = qs - w + i * BK;
        uint32_t st = sb + ((i - i0) & 1) * STG;
        CP_WAIT0();
        __syncthreads();
        if (i < i1) { load_tile(sb + ((i - i0 + 1) & 1) * STG, h, ts + BK, tid); CP_COMMIT(); }

        int jjlo = (Rlo - ts) >> 4; if (jjlo < 0) jjlo = 0;
        int jjhi = (Rhi - ts) >> 4; if (jjhi > 3) jjhi = 3;

        // ---- per-16-key-group pipeline: S -> exp -> PV ----
#pragma unroll
        for (int jj = 0; jj < 4; jj++) {
            if (jj < jjlo || jj > jjhi) continue;

            // S group (2 n8 blocks): s = Qh*Kh + Ql*Kh + Qh*Kl
            float s[2][4];
#pragma unroll
            for (int n = 0; n < 2; n++)
#pragma unroll
                for (int k = 0; k < 4; k++) s[n][k] = 0.f;

#pragma unroll
            for (int ks = 0; ks < 4; ks++) {
                uint32_t a = st + OKH + SWZ((16 * jj + keyo) * 128 + 32 * ks + dbq);
                uint32_t kh0[2], kh1[2], kl0[2], kl1[2];
                ldsm4(kh0[0], kh0[1], kh1[0], kh1[1], a);
                ldsm4(kl0[0], kl0[1], kl1[0], kl1[1], a + OKL);
                mma_bf(s[0], qh[ks], kh0);
                mma_bf(s[1], qh[ks], kh1);
                mma_bf(s[0], ql[ks], kh0);
                mma_bf(s[1], ql[ks], kh1);
                mma_bf(s[0], qh[ks], kl0);
                mma_bf(s[1], qh[ks], kl1);
            }

            // mask + exp2 + split P (fp16 hi/lo); C layout == next A layout
            uint32_t Ah[4], Al[4];
#pragma unroll
            for (int n = 0; n < 2; n++) {
                int c0 = ts + 16 * jj + 8 * n + 2 * tig, c1 = c0 + 1;
                float p00 = (c0 >= lo0 && c0 <= hi0) ? ex2f(s[n][0]) : 0.f;
                float p01 = (c1 >= lo0 && c1 <= hi0) ? ex2f(s[n][1]) : 0.f;
                float p10 = (c0 >= lo1 && c0 <= hi1) ? ex2f(s[n][2]) : 0.f;
                float p11 = (c1 >= lo1 && c1 <= hi1) ? ex2f(s[n][3]) : 0.f;
                l0 += p00 + p01; l1 += p10 + p11;
                uint32_t H0 = h2pack(p00, p01);
                uint32_t H1 = h2pack(p10, p11);
                float2 f0 = h2unpack(H0), f1 = h2unpack(H1);
                Ah[2 * n]     = H0;
                Ah[2 * n + 1] = H1;
                Al[2 * n]     = h2pack(p00 - f0.x, p01 - f0.y);
                Al[2 * n + 1] = h2pack(p10 - f1.x, p11 - f1.y);
            }

            // PV group: O += (Ph + Pl) * Vh
#pragma unroll
            for (int d2 = 0; d2 < 4; d2++) {
                uint32_t a = st + OVH + SWZ((16 * jj + keyq) * 128 + 32 * d2 + db2);
                uint32_t vh0[2], vh1[2];
                ldsm4t(vh0[0], vh0[1], vh1[0], vh1[1], a);
                mma_fp(o[2 * d2],     Ah, vh0);
                mma_fp(o[2 * d2 + 1], Ah, vh1);
                mma_fp(o[2 * d2],     Al, vh0);
                mma_fp(o[2 * d2 + 1], Al, vh1);
            }
        }
    }

    // ---- epilogue ----
    l0 += __shfl_xor_sync(0xffffffffu, l0, 1);
    l0 += __shfl_xor_sync(0xffffffffu, l0, 2);
    l1 += __shfl_xor_sync(0xffffffffu, l1, 1);
    l1 += __shfl_xor_sync(0xffffffffu, l1, 2);
    float inv0 = 1.0f / l0, inv1 = 1.0f / l1;

    float* ob0 = O + ((size_t)h * SEQ + r0) * DD;
    float* ob1 = O + ((size_t)h * SEQ + r1) * DD;
#pragma unroll
    for (int j = 0; j < 8; j++) {
        *(float2*)(ob0 + 8 * j + 2 * tig) = make_float2(o[j][0] * inv0, o[j][1] * inv0);
        *(float2*)(ob1 + 8 * j + 2 * tig) = make_float2(o[j][2] * inv1, o[j][3] * inv1);
    }
}

extern "C" void kernel_launch(void* const* d_in, const int* in_sizes, int n_in,
                              void* d_out, int out_size)
{
    const float* q = (const float*)d_in[0];
    const float* k = (const float*)d_in[1];
    const float* v = (const float*)d_in[2];
    const int* wsz = (const int*)d_in[4];
    float* out = (float*)d_out;

    prepass_kernel<<<(int)(KVN / 1024), 256>>>(k, v);

    cudaFuncSetAttribute(swa_mma_kernel,
                         cudaFuncAttributeMaxDynamicSharedMemorySize, SMEM_BYTES);
    dim3 grid(SEQ / BQ, HH);   // (128, 16)
    swa_mma_kernel<<<grid, 128, SMEM_BYTES>>>(q, wsz, out);
}

// round 9
// speedup vs baseline: 1.4547x; 1.1460x over previous
#include <cuda_runtime.h>
#include <cuda_bf16.h>
#include <cuda_fp16.h>
#include <cstdint>

// Sliding-window attention via mma.sync. S: bf16 3-term split (~fp32 exact).
// PV: single-term fp16 (P rn fp16, V fp16) -> O rel err ~3e-4 (gate 1e-3).
// R9 = R8 minus the P-lo PV term (-20% MMAs, less pack ALU).
// B=1, H=16, S=8192, D=64, window read on device.

static constexpr int HH  = 16;
static constexpr int SEQ = 8192;
static constexpr int DD  = 64;
static constexpr int BQ  = 64;
static constexpr int BK  = 64;
static constexpr size_t KVN = (size_t)HH * SEQ * DD;   // 8388608

__device__ __nv_bfloat16 g_kh[KVN];
__device__ __nv_bfloat16 g_kl[KVN];
__device__ __half        g_vh[KVN];

// ---------------- helpers ----------------
__device__ __forceinline__ uint32_t f2bf(float x) {
    uint32_t u = __float_as_uint(x);
    return (u + 0x7fffu + ((u >> 16) & 1u)) >> 16;
}
__device__ __forceinline__ float bf2f(uint32_t b) { return __uint_as_float(b << 16); }

// bf16x2 pack: upper = a, lower = b
__device__ __forceinline__ uint32_t cvt2(float a, float b) {
    uint32_t d;
    asm("cvt.rn.bf16x2.f32 %0, %1, %2;" : "=r"(d) : "f"(a), "f"(b));
    return d;
}
// fp16x2 pack: lower = a, upper = b
__device__ __forceinline__ uint32_t h2pack(float a, float b) {
    __half2 h = __floats2half2_rn(a, b);
    return *(uint32_t*)&h;
}
__device__ __forceinline__ float ex2f(float x) {
    float r;
    asm("ex2.approx.f32 %0, %1;" : "=f"(r) : "f"(x));
    return r;
}

__device__ __forceinline__ uint32_t smem_u32(const void* p) {
    uint32_t a;
    asm("{ .reg .u64 t; cvta.to.shared.u64 t, %1; cvt.u32.u64 %0, t; }" : "=r"(a) : "l"(p));
    return a;
}
#define SWZ(x) ((x) ^ (((x) >> 3) & 0x70))

__device__ __forceinline__ void cpasync16(uint32_t dst, const void* src, int sz) {
    asm volatile("cp.async.cg.shared.global [%0], [%1], 16, %2;"
                 :: "r"(dst), "l"(src), "r"(sz) : "memory");
}
#define CP_COMMIT() asm volatile("cp.async.commit_group;" ::: "memory")
#define CP_WAIT0()  asm volatile("cp.async.wait_group 0;" ::: "memory")

__device__ __forceinline__ void ldsm4(uint32_t& r0, uint32_t& r1, uint32_t& r2, uint32_t& r3,
                                      uint32_t addr) {
    asm volatile("ldmatrix.sync.aligned.m8n8.x4.shared.b16 {%0,%1,%2,%3}, [%4];"
                 : "=r"(r0), "=r"(r1), "=r"(r2), "=r"(r3) : "r"(addr));
}
__device__ __forceinline__ void ldsm4t(uint32_t& r0, uint32_t& r1, uint32_t& r2, uint32_t& r3,
                                       uint32_t addr) {
    asm volatile("ldmatrix.sync.aligned.m8n8.x4.trans.shared.b16 {%0,%1,%2,%3}, [%4];"
                 : "=r"(r0), "=r"(r1), "=r"(r2), "=r"(r3) : "r"(addr));
}
__device__ __forceinline__ void mma_bf(float* c, const uint32_t* a, const uint32_t* b) {
    asm volatile("mma.sync.aligned.m16n8k16.row.col.f32.bf16.bf16.f32 "
                 "{%0,%1,%2,%3}, {%4,%5,%6,%7}, {%8,%9}, {%0,%1,%2,%3};"
                 : "+f"(c[0]), "+f"(c[1]), "+f"(c[2]), "+f"(c[3])
                 : "r"(a[0]), "r"(a[1]), "r"(a[2]), "r"(a[3]), "r"(b[0]), "r"(b[1]));
}
__device__ __forceinline__ void mma_fp(float* c, const uint32_t* a, const uint32_t* b) {
    asm volatile("mma.sync.aligned.m16n8k16.row.col.f32.f16.f16.f32 "
                 "{%0,%1,%2,%3}, {%4,%5,%6,%7}, {%8,%9}, {%0,%1,%2,%3};"
                 : "+f"(c[0]), "+f"(c[1]), "+f"(c[2]), "+f"(c[3])
                 : "r"(a[0]), "r"(a[1]), "r"(a[2]), "r"(a[3]), "r"(b[0]), "r"(b[1]));
}

// ---------------- prepass: K fp32 -> bf16 hi/lo, V fp32 -> fp16 ----------------
__global__ void prepass_kernel(const float* __restrict__ K, const float* __restrict__ V) {
    size_t i = ((size_t)blockIdx.x * 256 + threadIdx.x) * 4;
    float4 k4 = *(const float4*)(K + i);
    float4 v4 = *(const float4*)(V + i);

    uint32_t kh0 = f2bf(k4.x), kh1 = f2bf(k4.y), kh2 = f2bf(k4.z), kh3 = f2bf(k4.w);
    uint2 khp = make_uint2(kh0 | (kh1 << 16), kh2 | (kh3 << 16));
    uint2 klp = make_uint2(f2bf(k4.x - bf2f(kh0)) | (f2bf(k4.y - bf2f(kh1)) << 16),
                           f2bf(k4.z - bf2f(kh2)) | (f2bf(k4.w - bf2f(kh3)) << 16));
    uint2 vhp = make_uint2(h2pack(v4.x, v4.y), h2pack(v4.z, v4.w));

    ((uint2*)g_kh)[i >> 2] = khp;
    ((uint2*)g_kl)[i >> 2] = klp;
    ((uint2*)g_vh)[i >> 2] = vhp;
}

// ---------------- main kernel ----------------
static constexpr int STG = 24576;
static constexpr int OKH = 0, OKL = 8192, OVH = 16384;
static constexpr int SMEM_BYTES = 2 * STG;   // 49152
// D^-1/2 * log2(e)
#define QSCALE 0.1803368801111204f

__device__ __forceinline__ void load_tile(uint32_t st, int h, int ts, int tid) {
#pragma unroll
    for (int c = 0; c < 4; c++) {
        int chunk = tid + 128 * c;
        int row = chunk >> 3;
        int col = (chunk & 7) * 16;
        int g = ts + row;
        bool ok = (unsigned)g < (unsigned)SEQ;
        int sz = ok ? 16 : 0;
        int gc = ok ? g : 0;
        size_t off = (((size_t)h * SEQ + gc) * DD) * 2 + col;
        uint32_t d = st + SWZ(row * 128 + col);
        cpasync16(d + OKH, (const char*)g_kh + off, sz);
        cpasync16(d + OKL, (const char*)g_kl + off, sz);
        cpasync16(d + OVH, (const char*)g_vh + off, sz);
    }
}

__global__ __launch_bounds__(128, 4)
void swa_mma_kernel(const float* __restrict__ Q,
                    const int*   __restrict__ wptr,
                    float*       __restrict__ O)
{
    extern __shared__ char smem[];
    const uint32_t sb = smem_u32(smem);
    const int tid = threadIdx.x;
    const int wid = tid >> 5, lane = tid & 31;
    const int gid = lane >> 2, tig = lane & 3;
    const int h  = blockIdx.y;
    const int qs = blockIdx.x * BQ;
    const int w  = *wptr;

    // ---- Q fragments (scaled, split bf16 hi/lo) ----
    uint32_t qh[4][4], ql[4][4];
    {
        const float* qb = Q + ((size_t)h * SEQ + qs) * DD;
        int m0 = wid * 16 + gid;
#pragma unroll
        for (int ks = 0; ks < 4; ks++) {
            int c = ks * 16 + 2 * tig;
#pragma unroll
            for (int half = 0; half < 2; half++)
#pragma unroll
                for (int rh = 0; rh < 2; rh++) {
                    const float* p = qb + (m0 + rh * 8) * DD + c + half * 8;
                    float x0 = p[0] * QSCALE, x1 = p[1] * QSCALE;
                    uint32_t H = cvt2(x1, x0);
                    float e0 = x0 - __uint_as_float(H << 16);
                    float e1 = x1 - __uint_as_float(H & 0xffff0000u);
                    int idx = half * 2 + rh;
                    qh[ks][idx] = H;
                    ql[ks][idx] = cvt2(e1, e0);
                }
        }
    }

    float o[8][4];
#pragma unroll
    for (int j = 0; j < 8; j++)
#pragma unroll
        for (int k = 0; k < 4; k++) o[j][k] = 0.f;
    float l0 = 0.f, l1 = 0.f;

    const int r0 = qs + wid * 16 + gid, r1 = r0 + 8;
    int lo0 = r0 - w; if (lo0 < 0) lo0 = 0;
    int hi0 = r0 + w; if (hi0 > SEQ - 1) hi0 = SEQ - 1;
    int lo1 = r1 - w; if (lo1 < 0) lo1 = 0;
    int hi1 = r1 + w; if (hi1 > SEQ - 1) hi1 = SEQ - 1;

    const int Rw = qs + wid * 16;
    int Rlo = Rw - w;      if (Rlo < 0) Rlo = 0;
    int Rhi = Rw + 15 + w; if (Rhi > SEQ - 1) Rhi = SEQ - 1;

    const int T = (BQ + 2 * w + BK - 1) / BK;
    int i0 = 0; while (qs - w + i0 * BK + BK <= 0) i0++;
    int i1 = T - 1; while (qs - w + i1 * BK >= SEQ) i1--;

    load_tile(sb, h, qs - w + i0 * BK, tid);
    CP_COMMIT();

    const int mi = lane >> 3, rr = lane & 7;
    const int keyo = ((mi >> 1) & 1) * 8 + rr;
    const int dbq  = (mi & 1) * 16;
    const int keyq = (mi & 1) * 8 + rr;
    const int db2  = ((mi >> 1) & 1) * 16;

    for (int i = i0; i <= i1; i++) {
        int ts = qs - w + i * BK;
        uint32_t st = sb + ((i - i0) & 1) * STG;
        CP_WAIT0();
        __syncthreads();
        if (i < i1) { load_tile(sb + ((i - i0 + 1) & 1) * STG, h, ts + BK, tid); CP_COMMIT(); }

        int jjlo = (Rlo - ts) >> 4; if (jjlo < 0) jjlo = 0;
        int jjhi = (Rhi - ts) >> 4; if (jjhi > 3) jjhi = 3;

        // ---- per-16-key-group pipeline: S -> exp -> PV ----
#pragma unroll
        for (int jj = 0; jj < 4; jj++) {
            if (jj < jjlo || jj > jjhi) continue;

            // S group (2 n8 blocks): s = Qh*Kh + Ql*Kh + Qh*Kl
            float s[2][4];
#pragma unroll
            for (int n = 0; n < 2; n++)
#pragma unroll
                for (int k = 0; k < 4; k++) s[n][k] = 0.f;

#pragma unroll
            for (int ks = 0; ks < 4; ks++) {
                uint32_t a = st + OKH + SWZ((16 * jj + keyo) * 128 + 32 * ks + dbq);
                uint32_t kh0[2], kh1[2], kl0[2], kl1[2];
                ldsm4(kh0[0], kh0[1], kh1[0], kh1[1], a);
                ldsm4(kl0[0], kl0[1], kl1[0], kl1[1], a + OKL);
                mma_bf(s[0], qh[ks], kh0);
                mma_bf(s[1], qh[ks], kh1);
                mma_bf(s[0], ql[ks], kh0);
                mma_bf(s[1], ql[ks], kh1);
                mma_bf(s[0], qh[ks], kl0);
                mma_bf(s[1], qh[ks], kl1);
            }

            // mask + exp2 + pack P to fp16 (single term); C layout == A layout
            uint32_t Ah[4];
#pragma unroll
            for (int n = 0; n < 2; n++) {
                int c0 = ts + 16 * jj + 8 * n + 2 * tig, c1 = c0 + 1;
                float p00 = (c0 >= lo0 && c0 <= hi0) ? ex2f(s[n][0]) : 0.f;
                float p01 = (c1 >= lo0 && c1 <= hi0) ? ex2f(s[n][1]) : 0.f;
                float p10 = (c0 >= lo1 && c0 <= hi1) ? ex2f(s[n][2]) : 0.f;
                float p11 = (c1 >= lo1 && c1 <= hi1) ? ex2f(s[n][3]) : 0.f;
                l0 += p00 + p01; l1 += p10 + p11;
                Ah[2 * n]     = h2pack(p00, p01);
                Ah[2 * n + 1] = h2pack(p10, p11);
            }

            // PV group: O += Ph * Vh
#pragma unroll
            for (int d2 = 0; d2 < 4; d2++) {
                uint32_t a = st + OVH + SWZ((16 * jj + keyq) * 128 + 32 * d2 + db2);
                uint32_t vh0[2], vh1[2];
                ldsm4t(vh0[0], vh0[1], vh1[0], vh1[1], a);
                mma_fp(o[2 * d2],     Ah, vh0);
                mma_fp(o[2 * d2 + 1], Ah, vh1);
            }
        }
    }

    // ---- epilogue ----
    l0 += __shfl_xor_sync(0xffffffffu, l0, 1);
    l0 += __shfl_xor_sync(0xffffffffu, l0, 2);
    l1 += __shfl_xor_sync(0xffffffffu, l1, 1);
    l1 += __shfl_xor_sync(0xffffffffu, l1, 2);
    float inv0 = 1.0f / l0, inv1 = 1.0f / l1;

    float* ob0 = O + ((size_t)h * SEQ + r0) * DD;
    float* ob1 = O + ((size_t)h * SEQ + r1) * DD;
#pragma unroll
    for (int j = 0; j < 8; j++) {
        *(float2*)(ob0 + 8 * j + 2 * tig) = make_float2(o[j][0] * inv0, o[j][1] * inv0);
        *(float2*)(ob1 + 8 * j + 2 * tig) = make_float2(o[j][2] * inv1, o[j][3] * inv1);
    }
}

extern "C" void kernel_launch(void* const* d_in, const int* in_sizes, int n_in,
                              void* d_out, int out_size)
{
    const float* q = (const float*)d_in[0];
    const float* k = (const float*)d_in[1];
    const float* v = (const float*)d_in[2];
    const int* wsz = (const int*)d_in[4];
    float* out = (float*)d_out;

    prepass_kernel<<<(int)(KVN / 1024), 256>>>(k, v);

    cudaFuncSetAttribute(swa_mma_kernel,
                         cudaFuncAttributeMaxDynamicSharedMemorySize, SMEM_BYTES);
    dim3 grid(SEQ / BQ, HH);   // (128, 16)
    swa_mma_kernel<<<grid, 128, SMEM_BYTES>>>(q, wsz, out);
}

// round 10
// speedup vs baseline: 1.7415x; 1.1972x over previous
#include <cuda_runtime.h>
#include <cuda_fp16.h>
#include <cstdint>

// Sliding-window attention via mma.sync, all-fp16 operands with Q error
// compensation:  S = (Qh + Ql) * fp16(K)   (2 fp16 MMA terms, exact in Q;
//                only K's 2^-12 rounding remains ~1.4e-4 in p)
//                O = fp16(P) * fp16(V)     (~2.9e-4)   => total ~3.2e-4.
// R10 = R9 with fp16-K 2-term S (-25% MMAs, -33% smem traffic) + interior-tile
// mask skip. B=1, H=16, S=8192, D=64, window read on device.

static constexpr int HH  = 16;
static constexpr int SEQ = 8192;
static constexpr int DD  = 64;
static constexpr int BQ  = 64;
static constexpr int BK  = 64;
static constexpr size_t KVN = (size_t)HH * SEQ * DD;   // 8388608

__device__ __half g_k16[KVN];
__device__ __half g_v16[KVN];

// ---------------- helpers ----------------
// fp16x2 pack: lower = a, upper = b
__device__ __forceinline__ uint32_t h2pack(float a, float b) {
    __half2 h = __floats2half2_rn(a, b);
    return *(uint32_t*)&h;
}
__device__ __forceinline__ float2 h2unpack(uint32_t u) {
    __half2 h = *(__half2*)&u;
    return __half22float2(h);
}
__device__ __forceinline__ float ex2f(float x) {
    float r;
    asm("ex2.approx.f32 %0, %1;" : "=f"(r) : "f"(x));
    return r;
}
__device__ __forceinline__ uint32_t smem_u32(const void* p) {
    uint32_t a;
    asm("{ .reg .u64 t; cvta.to.shared.u64 t, %1; cvt.u32.u64 %0, t; }" : "=r"(a) : "l"(p));
    return a;
}
#define SWZ(x) ((x) ^ (((x) >> 3) & 0x70))

__device__ __forceinline__ void cpasync16(uint32_t dst, const void* src, int sz) {
    asm volatile("cp.async.cg.shared.global [%0], [%1], 16, %2;"
                 :: "r"(dst), "l"(src), "r"(sz) : "memory");
}
#define CP_COMMIT() asm volatile("cp.async.commit_group;" ::: "memory")
#define CP_WAIT0()  asm volatile("cp.async.wait_group 0;" ::: "memory")

__device__ __forceinline__ void ldsm4(uint32_t& r0, uint32_t& r1, uint32_t& r2, uint32_t& r3,
                                      uint32_t addr) {
    asm volatile("ldmatrix.sync.aligned.m8n8.x4.shared.b16 {%0,%1,%2,%3}, [%4];"
                 : "=r"(r0), "=r"(r1), "=r"(r2), "=r"(r3) : "r"(addr));
}
__device__ __forceinline__ void ldsm4t(uint32_t& r0, uint32_t& r1, uint32_t& r2, uint32_t& r3,
                                       uint32_t addr) {
    asm volatile("ldmatrix.sync.aligned.m8n8.x4.trans.shared.b16 {%0,%1,%2,%3}, [%4];"
                 : "=r"(r0), "=r"(r1), "=r"(r2), "=r"(r3) : "r"(addr));
}
__device__ __forceinline__ void mma_fp(float* c, const uint32_t* a, const uint32_t* b) {
    asm volatile("mma.sync.aligned.m16n8k16.row.col.f32.f16.f16.f32 "
                 "{%0,%1,%2,%3}, {%4,%5,%6,%7}, {%8,%9}, {%0,%1,%2,%3};"
                 : "+f"(c[0]), "+f"(c[1]), "+f"(c[2]), "+f"(c[3])
                 : "r"(a[0]), "r"(a[1]), "r"(a[2]), "r"(a[3]), "r"(b[0]), "r"(b[1]));
}

// ---------------- prepass: K,V fp32 -> fp16 ----------------
__global__ void prepass_kernel(const float* __restrict__ K, const float* __restrict__ V) {
    size_t i = ((size_t)blockIdx.x * 256 + threadIdx.x) * 4;
    float4 k4 = *(const float4*)(K + i);
    float4 v4 = *(const float4*)(V + i);
    ((uint2*)g_k16)[i >> 2] = make_uint2(h2pack(k4.x, k4.y), h2pack(k4.z, k4.w));
    ((uint2*)g_v16)[i >> 2] = make_uint2(h2pack(v4.x, v4.y), h2pack(v4.z, v4.w));
}

// ---------------- main kernel ----------------
static constexpr int STG = 16384;
static constexpr int OK = 0, OV = 8192;
static constexpr int SMEM_BYTES = 2 * STG;   // 32768
// D^-1/2 * log2(e)
#define QSCALE 0.1803368801111204f

__device__ __forceinline__ void load_tile(uint32_t st, int h, int ts, int tid) {
#pragma unroll
    for (int c = 0; c < 4; c++) {
        int chunk = tid + 128 * c;
        int row = chunk >> 3;
        int col = (chunk & 7) * 16;
        int g = ts + row;
        bool ok = (unsigned)g < (unsigned)SEQ;
        int sz = ok ? 16 : 0;
        int gc = ok ? g : 0;
        size_t off = (((size_t)h * SEQ + gc) * DD) * 2 + col;
        uint32_t d = st + SWZ(row * 128 + col);
        cpasync16(d + OK, (const char*)g_k16 + off, sz);
        cpasync16(d + OV, (const char*)g_v16 + off, sz);
    }
}

__global__ __launch_bounds__(128, 4)
void swa_mma_kernel(const float* __restrict__ Q,
                    const int*   __restrict__ wptr,
                    float*       __restrict__ O)
{
    extern __shared__ char smem[];
    const uint32_t sb = smem_u32(smem);
    const int tid = threadIdx.x;
    const int wid = tid >> 5, lane = tid & 31;
    const int gid = lane >> 2, tig = lane & 3;
    const int h  = blockIdx.y;
    const int qs = blockIdx.x * BQ;
    const int w  = *wptr;

    // ---- Q fragments: scaled, split into fp16 hi + lo (exact sum) ----
    uint32_t qh[4][4], ql[4][4];
    {
        const float* qb = Q + ((size_t)h * SEQ + qs) * DD;
        int m0 = wid * 16 + gid;
#pragma unroll
        for (int ks = 0; ks < 4; ks++) {
            int c = ks * 16 + 2 * tig;
#pragma unroll
            for (int half = 0; half < 2; half++)
#pragma unroll
                for (int rh = 0; rh < 2; rh++) {
                    const float* p = qb + (m0 + rh * 8) * DD + c + half * 8;
                    float x0 = p[0] * QSCALE, x1 = p[1] * QSCALE;
                    uint32_t H = h2pack(x0, x1);
                    float2 f = h2unpack(H);
                    int idx = half * 2 + rh;
                    qh[ks][idx] = H;
                    ql[ks][idx] = h2pack(x0 - f.x, x1 - f.y);
                }
        }
    }

    float o[8][4];
#pragma unroll
    for (int j = 0; j < 8; j++)
#pragma unroll
        for (int k = 0; k < 4; k++) o[j][k] = 0.f;
    float l0 = 0.f, l1 = 0.f;

    const int r0 = qs + wid * 16 + gid, r1 = r0 + 8;
    int lo0 = r0 - w; if (lo0 < 0) lo0 = 0;
    int hi0 = r0 + w; if (hi0 > SEQ - 1) hi0 = SEQ - 1;
    int lo1 = r1 - w; if (lo1 < 0) lo1 = 0;
    int hi1 = r1 + w; if (hi1 > SEQ - 1) hi1 = SEQ - 1;

    const int Rw = qs + wid * 16;
    int Rlo = Rw - w;      if (Rlo < 0) Rlo = 0;
    int Rhi = Rw + 15 + w; if (Rhi > SEQ - 1) Rhi = SEQ - 1;

    const int T = (BQ + 2 * w + BK - 1) / BK;
    int i0 = 0; while (qs - w + i0 * BK + BK <= 0) i0++;
    int i1 = T - 1; while (qs - w + i1 * BK >= SEQ) i1--;

    load_tile(sb, h, qs - w + i0 * BK, tid);
    CP_COMMIT();

    const int mi = lane >> 3, rr = lane & 7;
    const int keyo = ((mi >> 1) & 1) * 8 + rr;
    const int dbq  = (mi & 1) * 16;
    const int keyq = (mi & 1) * 8 + rr;
    const int db2  = ((mi >> 1) & 1) * 16;

    for (int i = i0; i <= i1; i++) {
        int ts = qs - w + i * BK;
        uint32_t st = sb + ((i - i0) & 1) * STG;
        CP_WAIT0();
        __syncthreads();
        if (i < i1) { load_tile(sb + ((i - i0 + 1) & 1) * STG, h, ts + BK, tid); CP_COMMIT(); }

        int jjlo = (Rlo - ts) >> 4; if (jjlo < 0) jjlo = 0;
        int jjhi = (Rhi - ts) >> 4; if (jjhi > 3) jjhi = 3;

        // tile fully inside the band for every query row of this CTA?
        const bool inner = (ts >= qs + BQ - 1 - w) && (ts + BK - 1 <= qs + w) &&
                           (ts >= 0) && (ts + BK - 1 < SEQ);

        // ---- per-16-key-group pipeline: S -> exp -> PV ----
#pragma unroll
        for (int jj = 0; jj < 4; jj++) {
            if (jj < jjlo || jj > jjhi) continue;

            // S group: s = (Qh + Ql) * K16
            float s[2][4];
#pragma unroll
            for (int n = 0; n < 2; n++)
#pragma unroll
                for (int k = 0; k < 4; k++) s[n][k] = 0.f;

#pragma unroll
            for (int ks = 0; ks < 4; ks++) {
                uint32_t a = st + OK + SWZ((16 * jj + keyo) * 128 + 32 * ks + dbq);
                uint32_t k0[2], k1[2];
                ldsm4(k0[0], k0[1], k1[0], k1[1], a);
                mma_fp(s[0], qh[ks], k0);
                mma_fp(s[1], qh[ks], k1);
                mma_fp(s[0], ql[ks], k0);
                mma_fp(s[1], ql[ks], k1);
            }

            // mask + exp2 + pack P to fp16; C layout == next A layout
            uint32_t Ah[4];
            if (inner) {
#pragma unroll
                for (int n = 0; n < 2; n++) {
                    float p00 = ex2f(s[n][0]);
                    float p01 = ex2f(s[n][1]);
                    float p10 = ex2f(s[n][2]);
                    float p11 = ex2f(s[n][3]);
                    l0 += p00 + p01; l1 += p10 + p11;
                    Ah[2 * n]     = h2pack(p00, p01);
                    Ah[2 * n + 1] = h2pack(p10, p11);
                }
            } else {
#pragma unroll
                for (int n = 0; n < 2; n++) {
                    int c0 = ts + 16 * jj + 8 * n + 2 * tig, c1 = c0 + 1;
                    float p00 = (c0 >= lo0 && c0 <= hi0) ? ex2f(s[n][0]) : 0.f;
                    float p01 = (c1 >= lo0 && c1 <= hi0) ? ex2f(s[n][1]) : 0.f;
                    float p10 = (c0 >= lo1 && c0 <= hi1) ? ex2f(s[n][2]) : 0.f;
                    float p11 = (c1 >= lo1 && c1 <= hi1) ? ex2f(s[n][3]) : 0.f;
                    l0 += p00 + p01; l1 += p10 + p11;
                    Ah[2 * n]     = h2pack(p00, p01);
                    Ah[2 * n + 1] = h2pack(p10, p11);
                }
            }

            // PV group: O += Ph * V16
#pragma unroll
            for (int d2 = 0; d2 < 4; d2++) {
                uint32_t a = st + OV + SWZ((16 * jj + keyq) * 128 + 32 * d2 + db2);
                uint32_t v0[2], v1[2];
                ldsm4t(v0[0], v0[1], v1[0], v1[1], a);
                mma_fp(o[2 * d2],     Ah, v0);
                mma_fp(o[2 * d2 + 1], Ah, v1);
            }
        }
    }

    // ---- epilogue ----
    l0 += __shfl_xor_sync(0xffffffffu, l0, 1);
    l0 += __shfl_xor_sync(0xffffffffu, l0, 2);
    l1 += __shfl_xor_sync(0xffffffffu, l1, 1);
    l1 += __shfl_xor_sync(0xffffffffu, l1, 2);
    float inv0 = 1.0f / l0, inv1 = 1.0f / l1;

    float* ob0 = O + ((size_t)h * SEQ + r0) * DD;
    float* ob1 = O + ((size_t)h * SEQ + r1) * DD;
#pragma unroll
    for (int j = 0; j < 8; j++) {
        *(float2*)(ob0 + 8 * j + 2 * tig) = make_float2(o[j][0] * inv0, o[j][1] * inv0);
        *(float2*)(ob1 + 8 * j + 2 * tig) = make_float2(o[j][2] * inv1, o[j][3] * inv1);
    }
}

extern "C" void kernel_launch(void* const* d_in, const int* in_sizes, int n_in,
                              void* d_out, int out_size)
{
    const float* q = (const float*)d_in[0];
    const float* k = (const float*)d_in[1];
    const float* v = (const float*)d_in[2];
    const int* wsz = (const int*)d_in[4];
    float* out = (float*)d_out;

    prepass_kernel<<<(int)(KVN / 1024), 256>>>(k, v);

    cudaFuncSetAttribute(swa_mma_kernel,
                         cudaFuncAttributeMaxDynamicSharedMemorySize, SMEM_BYTES);
    dim3 grid(SEQ / BQ, HH);   // (128, 16)
    swa_mma_kernel<<<grid, 128, SMEM_BYTES>>>(q, wsz, out);
}

// round 11
// speedup vs baseline: 2.1944x; 1.2600x over previous
#include <cuda_runtime.h>
#include <cuda_fp16.h>
#include <cstdint>

// Sliding-window attention via mma.sync, all-fp16 operands:
//   S = fp16(Q)*fp16(K)  (1 term; Q+K rounding ~2e-4 in p)
//   O = fp16(P)*fp16(V)  (~2.9e-4)          => total ~4.0e-4 (gate 1e-3).
// R11 = R10 minus the Q-lo S term (-33% MMAs).
// B=1, H=16, S=8192, D=64, window read on device.

static constexpr int HH  = 16;
static constexpr int SEQ = 8192;
static constexpr int DD  = 64;
static constexpr int BQ  = 64;
static constexpr int BK  = 64;
static constexpr size_t KVN = (size_t)HH * SEQ * DD;   // 8388608

__device__ __half g_k16[KVN];
__device__ __half g_v16[KVN];

// ---------------- helpers ----------------
// fp16x2 pack: lower = a, upper = b
__device__ __forceinline__ uint32_t h2pack(float a, float b) {
    __half2 h = __floats2half2_rn(a, b);
    return *(uint32_t*)&h;
}
__device__ __forceinline__ float ex2f(float x) {
    float r;
    asm("ex2.approx.f32 %0, %1;" : "=f"(r) : "f"(x));
    return r;
}
__device__ __forceinline__ uint32_t smem_u32(const void* p) {
    uint32_t a;
    asm("{ .reg .u64 t; cvta.to.shared.u64 t, %1; cvt.u32.u64 %0, t; }" : "=r"(a) : "l"(p));
    return a;
}
#define SWZ(x) ((x) ^ (((x) >> 3) & 0x70))

__device__ __forceinline__ void cpasync16(uint32_t dst, const void* src, int sz) {
    asm volatile("cp.async.cg.shared.global [%0], [%1], 16, %2;"
                 :: "r"(dst), "l"(src), "r"(sz) : "memory");
}
#define CP_COMMIT() asm volatile("cp.async.commit_group;" ::: "memory")
#define CP_WAIT0()  asm volatile("cp.async.wait_group 0;" ::: "memory")

__device__ __forceinline__ void ldsm4(uint32_t& r0, uint32_t& r1, uint32_t& r2, uint32_t& r3,
                                      uint32_t addr) {
    asm volatile("ldmatrix.sync.aligned.m8n8.x4.shared.b16 {%0,%1,%2,%3}, [%4];"
                 : "=r"(r0), "=r"(r1), "=r"(r2), "=r"(r3) : "r"(addr));
}
__device__ __forceinline__ void ldsm4t(uint32_t& r0, uint32_t& r1, uint32_t& r2, uint32_t& r3,
                                       uint32_t addr) {
    asm volatile("ldmatrix.sync.aligned.m8n8.x4.trans.shared.b16 {%0,%1,%2,%3}, [%4];"
                 : "=r"(r0), "=r"(r1), "=r"(r2), "=r"(r3) : "r"(addr));
}
__device__ __forceinline__ void mma_fp(float* c, const uint32_t* a, const uint32_t* b) {
    asm volatile("mma.sync.aligned.m16n8k16.row.col.f32.f16.f16.f32 "
                 "{%0,%1,%2,%3}, {%4,%5,%6,%7}, {%8,%9}, {%0,%1,%2,%3};"
                 : "+f"(c[0]), "+f"(c[1]), "+f"(c[2]), "+f"(c[3])
                 : "r"(a[0]), "r"(a[1]), "r"(a[2]), "r"(a[3]), "r"(b[0]), "r"(b[1]));
}

// ---------------- prepass: K,V fp32 -> fp16 ----------------
__global__ void prepass_kernel(const float* __restrict__ K, const float* __restrict__ V) {
    size_t i = ((size_t)blockIdx.x * 256 + threadIdx.x) * 4;
    float4 k4 = *(const float4*)(K + i);
    float4 v4 = *(const float4*)(V + i);
    ((uint2*)g_k16)[i >> 2] = make_uint2(h2pack(k4.x, k4.y), h2pack(k4.z, k4.w));
    ((uint2*)g_v16)[i >> 2] = make_uint2(h2pack(v4.x, v4.y), h2pack(v4.z, v4.w));
}

// ---------------- main kernel ----------------
static constexpr int STG = 16384;
static constexpr int OK = 0, OV = 8192;
static constexpr int SMEM_BYTES = 2 * STG;   // 32768
// D^-1/2 * log2(e)
#define QSCALE 0.1803368801111204f

__device__ __forceinline__ void load_tile(uint32_t st, int h, int ts, int tid) {
#pragma unroll
    for (int c = 0; c < 4; c++) {
        int chunk = tid + 128 * c;
        int row = chunk >> 3;
        int col = (chunk & 7) * 16;
        int g = ts + row;
        bool ok = (unsigned)g < (unsigned)SEQ;
        int sz = ok ? 16 : 0;
        int gc = ok ? g : 0;
        size_t off = (((size_t)h * SEQ + gc) * DD) * 2 + col;
        uint32_t d = st + SWZ(row * 128 + col);
        cpasync16(d + OK, (const char*)g_k16 + off, sz);
        cpasync16(d + OV, (const char*)g_v16 + off, sz);
    }
}

__global__ __launch_bounds__(128, 4)
void swa_mma_kernel(const float* __restrict__ Q,
                    const int*   __restrict__ wptr,
                    float*       __restrict__ O)
{
    extern __shared__ char smem[];
    const uint32_t sb = smem_u32(smem);
    const int tid = threadIdx.x;
    const int wid = tid >> 5, lane = tid & 31;
    const int gid = lane >> 2, tig = lane & 3;
    const int h  = blockIdx.y;
    const int qs = blockIdx.x * BQ;
    const int w  = *wptr;

    // ---- Q fragments: scaled, fp16 ----
    uint32_t qh[4][4];
    {
        const float* qb = Q + ((size_t)h * SEQ + qs) * DD;
        int m0 = wid * 16 + gid;
#pragma unroll
        for (int ks = 0; ks < 4; ks++) {
            int c = ks * 16 + 2 * tig;
#pragma unroll
            for (int half = 0; half < 2; half++)
#pragma unroll
                for (int rh = 0; rh < 2; rh++) {
                    const float* p = qb + (m0 + rh * 8) * DD + c + half * 8;
                    qh[ks][half * 2 + rh] = h2pack(p[0] * QSCALE, p[1] * QSCALE);
                }
        }
    }

    float o[8][4];
#pragma unroll
    for (int j = 0; j < 8; j++)
#pragma unroll
        for (int k = 0; k < 4; k++) o[j][k] = 0.f;
    float l0 = 0.f, l1 = 0.f;

    const int r0 = qs + wid * 16 + gid, r1 = r0 + 8;
    int lo0 = r0 - w; if (lo0 < 0) lo0 = 0;
    int hi0 = r0 + w; if (hi0 > SEQ - 1) hi0 = SEQ - 1;
    int lo1 = r1 - w; if (lo1 < 0) lo1 = 0;
    int hi1 = r1 + w; if (hi1 > SEQ - 1) hi1 = SEQ - 1;

    const int Rw = qs + wid * 16;
    int Rlo = Rw - w;      if (Rlo < 0) Rlo = 0;
    int Rhi = Rw + 15 + w; if (Rhi > SEQ - 1) Rhi = SEQ - 1;

    const int T = (BQ + 2 * w + BK - 1) / BK;
    int i0 = 0; while (qs - w + i0 * BK + BK <= 0) i0++;
    int i1 = T - 1; while (qs - w + i1 * BK >= SEQ) i1--;

    load_tile(sb, h, qs - w + i0 * BK, tid);
    CP_COMMIT();

    const int mi = lane >> 3, rr = lane & 7;
    const int keyo = ((mi >> 1) & 1) * 8 + rr;
    const int dbq  = (mi & 1) * 16;
    const int keyq = (mi & 1) * 8 + rr;
    const int db2  = ((mi >> 1) & 1) * 16;

    for (int i = i0; i <= i1; i++) {
        int ts = qs - w + i * BK;
        uint32_t st = sb + ((i - i0) & 1) * STG;
        CP_WAIT0();
        __syncthreads();
        if (i < i1) { load_tile(sb + ((i - i0 + 1) & 1) * STG, h, ts + BK, tid); CP_COMMIT(); }

        int jjlo = (Rlo - ts) >> 4; if (jjlo < 0) jjlo = 0;
        int jjhi = (Rhi - ts) >> 4; if (jjhi > 3) jjhi = 3;

        // tile fully inside the band for every query row of this CTA?
        const bool inner = (ts >= qs + BQ - 1 - w) && (ts + BK - 1 <= qs + w) &&
                           (ts >= 0) && (ts + BK - 1 < SEQ);

        // ---- per-16-key-group pipeline: S -> exp -> PV ----
#pragma unroll
        for (int jj = 0; jj < 4; jj++) {
            if (jj < jjlo || jj > jjhi) continue;

            // S group: s = Q16 * K16
            float s[2][4];
#pragma unroll
            for (int n = 0; n < 2; n++)
#pragma unroll
                for (int k = 0; k < 4; k++) s[n][k] = 0.f;

#pragma unroll
            for (int ks = 0; ks < 4; ks++) {
                uint32_t a = st + OK + SWZ((16 * jj + keyo) * 128 + 32 * ks + dbq);
                uint32_t k0[2], k1[2];
                ldsm4(k0[0], k0[1], k1[0], k1[1], a);
                mma_fp(s[0], qh[ks], k0);
                mma_fp(s[1], qh[ks], k1);
            }

            // mask + exp2 + pack P to fp16; C layout == next A layout
            uint32_t Ah[4];
            if (inner) {
#pragma unroll
                for (int n = 0; n < 2; n++) {
                    float p00 = ex2f(s[n][0]);
                    float p01 = ex2f(s[n][1]);
                    float p10 = ex2f(s[n][2]);
                    float p11 = ex2f(s[n][3]);
                    l0 += p00 + p01; l1 += p10 + p11;
                    Ah[2 * n]     = h2pack(p00, p01);
                    Ah[2 * n + 1] = h2pack(p10, p11);
                }
            } else {
#pragma unroll
                for (int n = 0; n < 2; n++) {
                    int c0 = ts + 16 * jj + 8 * n + 2 * tig, c1 = c0 + 1;
                    float p00 = (c0 >= lo0 && c0 <= hi0) ? ex2f(s[n][0]) : 0.f;
                    float p01 = (c1 >= lo0 && c1 <= hi0) ? ex2f(s[n][1]) : 0.f;
                    float p10 = (c0 >= lo1 && c0 <= hi1) ? ex2f(s[n][2]) : 0.f;
                    float p11 = (c1 >= lo1 && c1 <= hi1) ? ex2f(s[n][3]) : 0.f;
                    l0 += p00 + p01; l1 += p10 + p11;
                    Ah[2 * n]     = h2pack(p00, p01);
                    Ah[2 * n + 1] = h2pack(p10, p11);
                }
            }

            // PV group: O += Ph * V16
#pragma unroll
            for (int d2 = 0; d2 < 4; d2++) {
                uint32_t a = st + OV + SWZ((16 * jj + keyq) * 128 + 32 * d2 + db2);
                uint32_t v0[2], v1[2];
                ldsm4t(v0[0], v0[1], v1[0], v1[1], a);
                mma_fp(o[2 * d2],     Ah, v0);
                mma_fp(o[2 * d2 + 1], Ah, v1);
            }
        }
    }

    // ---- epilogue ----
    l0 += __shfl_xor_sync(0xffffffffu, l0, 1);
    l0 += __shfl_xor_sync(0xffffffffu, l0, 2);
    l1 += __shfl_xor_sync(0xffffffffu, l1, 1);
    l1 += __shfl_xor_sync(0xffffffffu, l1, 2);
    float inv0 = 1.0f / l0, inv1 = 1.0f / l1;

    float* ob0 = O + ((size_t)h * SEQ + r0) * DD;
    float* ob1 = O + ((size_t)h * SEQ + r1) * DD;
#pragma unroll
    for (int j = 0; j < 8; j++) {
        *(float2*)(ob0 + 8 * j + 2 * tig) = make_float2(o[j][0] * inv0, o[j][1] * inv0);
        *(float2*)(ob1 + 8 * j + 2 * tig) = make_float2(o[j][2] * inv1, o[j][3] * inv1);
    }
}

extern "C" void kernel_launch(void* const* d_in, const int* in_sizes, int n_in,
                              void* d_out, int out_size)
{
    const float* q = (const float*)d_in[0];
    const float* k = (const float*)d_in[1];
    const float* v = (const float*)d_in[2];
    const int* wsz = (const int*)d_in[4];
    float* out = (float*)d_out;

    prepass_kernel<<<(int)(KVN / 1024), 256>>>(k, v);

    cudaFuncSetAttribute(swa_mma_kernel,
                         cudaFuncAttributeMaxDynamicSharedMemorySize, SMEM_BYTES);
    dim3 grid(SEQ / BQ, HH);   // (128, 16)
    swa_mma_kernel<<<grid, 128, SMEM_BYTES>>>(q, wsz, out);
}